// round 15
// baseline (speedup 1.0000x reference)
#include <cuda_runtime.h>
#include <cuda_bf16.h>
#include <cuda_fp16.h>
#include <math.h>

#define N_NODES 100000
#define N_EDGES 20000
#define N_INC   800000
#define D_IN    256
#define D_HID   16
#define D_OUT   40
#define PAD_E   128
#define PAD_V   64

// ---------------- scratch (device globals) ----------------
__device__ __half2 g_XW1h[(size_t)N_NODES * (D_HID / 2)]; // H@W1, fp16, 32B rows
__device__ __half2 g_e1h [(size_t)N_EDGES * (D_HID / 2)]; // e_feat1, fp16, 32B rows
__device__ __half2 g_X2h [(size_t)N_NODES * (D_HID / 2)]; // x=relu(...), fp16, 32B rows
__device__ __half2 g_e2h [(size_t)N_EDGES * (D_HID / 2)]; // e_feat2, fp16, 32B rows
__device__ int     g_cnt_e[N_EDGES];   // zero-init; re-zeroed by ng2 each call
__device__ int     g_cnt_v[N_NODES];   // zero-init; re-zeroed by ng2 each call
__device__ int2    g_buf_e[(size_t)N_EDGES * PAD_E];      // {node idx, w bits}
__device__ int     g_buf_v[(size_t)N_NODES * PAD_V];      // edge idx

// ---------------- GEMM1 + bucket fill (merged; disjoint block ranges) --------
#define GEMM1_BLOCKS ((N_NODES + 255) / 256)
#define FILL_BLOCKS  ((N_INC + 255) / 256)
__global__ void gemm1_fill_kernel(const float* __restrict__ H, const float* __restrict__ W1,
                                  const int* __restrict__ ni, const int* __restrict__ ei,
                                  const float* __restrict__ w) {
    if (blockIdx.x >= GEMM1_BLOCKS) {
        int i = (blockIdx.x - GEMM1_BLOCKS) * blockDim.x + threadIdx.x;
        if (i >= N_INC) return;
        int v = __ldg(&ni[i]);
        int e = __ldg(&ei[i]);
        float wv = __ldg(&w[v]);
        int se = atomicAdd(&g_cnt_e[e], 1);
        if (se < PAD_E) g_buf_e[(size_t)e * PAD_E + se] = make_int2(v, __float_as_int(wv));
        int sv = atomicAdd(&g_cnt_v[v], 1);
        if (sv < PAD_V) g_buf_v[(size_t)v * PAD_V + sv] = e;
        return;
    }
    __shared__ float sW[D_IN * D_HID];
    for (int i = threadIdx.x; i < D_IN * D_HID; i += blockDim.x) sW[i] = W1[i];
    __syncthreads();

    int row = blockIdx.x * blockDim.x + threadIdx.x;
    if (row >= N_NODES) return;

    unsigned long long acc2[8];
#pragma unroll
    for (int j = 0; j < 8; j++)
        asm("mov.b64 %0, {%1, %1};" : "=l"(acc2[j]) : "f"(0.f));

    const float4* hp = reinterpret_cast<const float4*>(H + (size_t)row * D_IN);
#pragma unroll 4
    for (int k4 = 0; k4 < D_IN / 4; k4++) {
        float4 hv = __ldcs(&hp[k4]);
        float xs[4] = {hv.x, hv.y, hv.z, hv.w};
#pragma unroll
        for (int c = 0; c < 4; c++) {
            unsigned long long x2;
            asm("mov.b64 %0, {%1, %1};" : "=l"(x2) : "f"(xs[c]));
            const unsigned long long* w2 =
                reinterpret_cast<const unsigned long long*>(&sW[(k4 * 4 + c) * D_HID]);
#pragma unroll
            for (int j = 0; j < 8; j++) {
                unsigned long long wv = w2[j];
                asm("fma.rn.f32x2 %0, %1, %2, %0;" : "+l"(acc2[j]) : "l"(x2), "l"(wv));
            }
        }
    }
    float a[D_HID];
#pragma unroll
    for (int j = 0; j < 8; j++)
        asm("mov.b64 {%0, %1}, %2;" : "=f"(a[2 * j]), "=f"(a[2 * j + 1]) : "l"(acc2[j]));
    uint4 r0, r1;
    ((__half2*)&r0)[0] = __floats2half2_rn(a[0],  a[1]);
    ((__half2*)&r0)[1] = __floats2half2_rn(a[2],  a[3]);
    ((__half2*)&r0)[2] = __floats2half2_rn(a[4],  a[5]);
    ((__half2*)&r0)[3] = __floats2half2_rn(a[6],  a[7]);
    ((__half2*)&r1)[0] = __floats2half2_rn(a[8],  a[9]);
    ((__half2*)&r1)[1] = __floats2half2_rn(a[10], a[11]);
    ((__half2*)&r1)[2] = __floats2half2_rn(a[12], a[13]);
    ((__half2*)&r1)[3] = __floats2half2_rn(a[14], a[15]);
    uint4* op = reinterpret_cast<uint4*>(g_XW1h) + (size_t)row * 2;
    op[0] = r0;
    op[1] = r1;
}

// ---------------- split-edge gather body (2 warps per edge, smem combine) ----
// Block: 256 threads = 8 warps = 4 edges. Warp sub in {0,1} takes chunks of
// parity sub. SRC rows: fp16 32B (4 uint2). DST: g_e1h or g_e2h.
template <bool DUMMY>
__device__ __forceinline__ void edge_gather_split(const uint2* __restrict__ xr,
                                                  __half2* __restrict__ dst) {
    __shared__ float4 sA[4][2][4];
    __shared__ float  sS[4][2];

    int wib  = threadIdx.x >> 5;     // warp in block: 0..7
    int eslot = wib >> 1;            // 0..3
    int sub   = wib & 1;
    int lane  = threadIdx.x & 31;
    int g = lane >> 2, c = lane & 3;
    int e = blockIdx.x * 4 + eslot;  // N_EDGES divisible by 4

    cudaGridDependencySynchronize();

    int cnt = min(__ldg(&g_cnt_e[e]), PAD_E);
    const int2* buf = g_buf_e + (size_t)e * PAD_E;
    float4 acc = make_float4(0.f, 0.f, 0.f, 0.f);
    float wsum = 0.f;
    int mb = sub * 8;
    for (; mb + 8 <= cnt; mb += 16) {
        int2 p = __ldg(&buf[mb + g]);
        float wv = __int_as_float(p.y);
        uint2 r = __ldg(&xr[(size_t)p.x * 4 + c]);
        float2 f0 = __half22float2(*reinterpret_cast<__half2*>(&r.x));
        float2 f1 = __half22float2(*reinterpret_cast<__half2*>(&r.y));
        acc.x += wv * f0.x; acc.y += wv * f0.y; acc.z += wv * f1.x; acc.w += wv * f1.y;
        wsum += wv;
    }
    if (mb + g < cnt) {              // partial tail chunk (owned by one sub only)
        int2 p = __ldg(&buf[mb + g]);
        float wv = __int_as_float(p.y);
        uint2 r = __ldg(&xr[(size_t)p.x * 4 + c]);
        float2 f0 = __half22float2(*reinterpret_cast<__half2*>(&r.x));
        float2 f1 = __half22float2(*reinterpret_cast<__half2*>(&r.y));
        acc.x += wv * f0.x; acc.y += wv * f0.y; acc.z += wv * f1.x; acc.w += wv * f1.y;
        wsum += wv;
    }
#pragma unroll
    for (int st = 4; st < 32; st <<= 1) {
        acc.x += __shfl_xor_sync(0xFFFFFFFFu, acc.x, st);
        acc.y += __shfl_xor_sync(0xFFFFFFFFu, acc.y, st);
        acc.z += __shfl_xor_sync(0xFFFFFFFFu, acc.z, st);
        acc.w += __shfl_xor_sync(0xFFFFFFFFu, acc.w, st);
        wsum  += __shfl_xor_sync(0xFFFFFFFFu, wsum,  st);
    }
    if (g == 0) sA[eslot][sub][c] = acc;          // lanes 0..3 (c) hold group-c totals
    if (lane == 0) sS[eslot][sub] = wsum;
    __syncthreads();
    if (sub == 0 && g == 0) {
        float4 a0 = sA[eslot][0][c], a1 = sA[eslot][1][c];
        float ws = sS[eslot][0] + sS[eslot][1];
        float inv = __frcp_rn(fmaxf(ws, 1e-6f));
        uint2 r;
        *reinterpret_cast<__half2*>(&r.x) = __floats2half2_rn((a0.x + a1.x) * inv, (a0.y + a1.y) * inv);
        *reinterpret_cast<__half2*>(&r.y) = __floats2half2_rn((a0.z + a1.z) * inv, (a0.w + a1.w) * inv);
        reinterpret_cast<uint2*>(dst)[(size_t)e * 4 + c] = r;
    }
}

__global__ void edge_gather1_kernel() {
    edge_gather_split<true>(reinterpret_cast<const uint2*>(g_XW1h), g_e1h);
}
__global__ void edge_gather2_kernel() {
    edge_gather_split<true>(reinterpret_cast<const uint2*>(g_X2h), g_e2h);
}

// ---------------- node gather 1: TWO nodes/warp; x=relu(mean+b1) -> fp16 -----
__global__ void node_gather1_kernel(const float* __restrict__ b1) {
    int warp = (blockIdx.x * blockDim.x + threadIdx.x) >> 5;
    int lane = threadIdx.x & 31;
    int half = lane >> 4, l = lane & 15;
    int v = warp * 2 + half;
    int g = l >> 2, c = l & 3;
    float bias = __ldg(&b1[l]);     // harness input: safe pre-sync

    cudaGridDependencySynchronize();
    if (v >= N_NODES) return;

    int cnt = min(__ldg(&g_cnt_v[v]), PAD_V);
    const int* buf = g_buf_v + (size_t)v * PAD_V;
    const uint2* er = reinterpret_cast<const uint2*>(g_e1h);
    float4 acc = make_float4(0.f, 0.f, 0.f, 0.f);
    int mb = 0;
    for (; mb + 4 <= cnt; mb += 4) {
        int e0 = __ldg(&buf[mb + g]);
        uint2 r = __ldg(&er[(size_t)e0 * 4 + c]);
        float2 f0 = __half22float2(*reinterpret_cast<__half2*>(&r.x));
        float2 f1 = __half22float2(*reinterpret_cast<__half2*>(&r.y));
        acc.x += f0.x; acc.y += f0.y; acc.z += f1.x; acc.w += f1.y;
    }
    if (mb + g < cnt) {
        int e0 = __ldg(&buf[mb + g]);
        uint2 r = __ldg(&er[(size_t)e0 * 4 + c]);
        float2 f0 = __half22float2(*reinterpret_cast<__half2*>(&r.x));
        float2 f1 = __half22float2(*reinterpret_cast<__half2*>(&r.y));
        acc.x += f0.x; acc.y += f0.y; acc.z += f1.x; acc.w += f1.y;
    }
#pragma unroll
    for (int st = 4; st < 16; st <<= 1) {
        acc.x += __shfl_xor_sync(0xFFFFFFFFu, acc.x, st);
        acc.y += __shfl_xor_sync(0xFFFFFFFFu, acc.y, st);
        acc.z += __shfl_xor_sync(0xFFFFFFFFu, acc.z, st);
        acc.w += __shfl_xor_sync(0xFFFFFFFFu, acc.w, st);
    }
    if (g == 0) {
        float b0  = __shfl_sync(0xFFFFFFFFu, bias, (half << 4) + c * 4 + 0);
        float bb1 = __shfl_sync(0xFFFFFFFFu, bias, (half << 4) + c * 4 + 1);
        float b2v = __shfl_sync(0xFFFFFFFFu, bias, (half << 4) + c * 4 + 2);
        float b3  = __shfl_sync(0xFFFFFFFFu, bias, (half << 4) + c * 4 + 3);
        float invd = __frcp_rn(fmaxf((float)cnt, 1.f));
        float x0 = fmaxf(acc.x * invd + b0, 0.f);
        float x1 = fmaxf(acc.y * invd + bb1, 0.f);
        float x2 = fmaxf(acc.z * invd + b2v, 0.f);
        float x3 = fmaxf(acc.w * invd + b3, 0.f);
        uint2 r;
        *reinterpret_cast<__half2*>(&r.x) = __floats2half2_rn(x0, x1);
        *reinterpret_cast<__half2*>(&r.y) = __floats2half2_rn(x2, x3);
        reinterpret_cast<uint2*>(g_X2h)[(size_t)v * 4 + c] = r;
    }
}

// ---------------- node gather 2: TWO nodes/warp + W2 + b2 + log_softmax ------
__global__ void node_gather2_fin_kernel(float* __restrict__ out,
                                        const float* __restrict__ W2,
                                        const float* __restrict__ b2) {
    __shared__ float sW[D_HID * D_OUT];
    for (int i = threadIdx.x; i < D_HID * D_OUT; i += blockDim.x) sW[i] = W2[i];
    __syncthreads();

    cudaGridDependencySynchronize();

    int warp = (blockIdx.x * blockDim.x + threadIdx.x) >> 5;
    int lane = threadIdx.x & 31;
    int half = lane >> 4, l = lane & 15;
    int v = warp * 2 + half;
    if (v >= N_NODES) return;
    int cnt = min(__ldg(&g_cnt_v[v]), PAD_V);
    if (l == 0) g_cnt_v[v] = 0;
    if (l == 1 && v < N_EDGES) g_cnt_e[v] = 0;
    int g = l >> 2, c = l & 3;

    const int* buf = g_buf_v + (size_t)v * PAD_V;
    const uint2* er = reinterpret_cast<const uint2*>(g_e2h);
    float4 acc = make_float4(0.f, 0.f, 0.f, 0.f);
    int mb = 0;
    for (; mb + 4 <= cnt; mb += 4) {
        int e0 = __ldg(&buf[mb + g]);
        uint2 r = __ldg(&er[(size_t)e0 * 4 + c]);
        float2 f0 = __half22float2(*reinterpret_cast<__half2*>(&r.x));
        float2 f1 = __half22float2(*reinterpret_cast<__half2*>(&r.y));
        acc.x += f0.x; acc.y += f0.y; acc.z += f1.x; acc.w += f1.y;
    }
    if (mb + g < cnt) {
        int e0 = __ldg(&buf[mb + g]);
        uint2 r = __ldg(&er[(size_t)e0 * 4 + c]);
        float2 f0 = __half22float2(*reinterpret_cast<__half2*>(&r.x));
        float2 f1 = __half22float2(*reinterpret_cast<__half2*>(&r.y));
        acc.x += f0.x; acc.y += f0.y; acc.z += f1.x; acc.w += f1.y;
    }
#pragma unroll
    for (int st = 4; st < 16; st <<= 1) {
        acc.x += __shfl_xor_sync(0xFFFFFFFFu, acc.x, st);
        acc.y += __shfl_xor_sync(0xFFFFFFFFu, acc.y, st);
        acc.z += __shfl_xor_sync(0xFFFFFFFFu, acc.z, st);
        acc.w += __shfl_xor_sync(0xFFFFFFFFu, acc.w, st);
    }
    float invd = __frcp_rn(fmaxf((float)cnt, 1.f));
    float4 vf;
    vf.x = acc.x * invd; vf.y = acc.y * invd; vf.z = acc.z * invd; vf.w = acc.w * invd;

    bool has3 = l < (D_OUT - 32);
    float o0 = 0.f, o1 = 0.f, o2 = 0.f;
#pragma unroll
    for (int k = 0; k < D_HID; k++) {
        int src = (half << 4) + (k >> 2);
        float comp = (k & 3) == 0 ? vf.x : (k & 3) == 1 ? vf.y : (k & 3) == 2 ? vf.z : vf.w;
        float xk = __shfl_sync(0xFFFFFFFFu, comp, src);
        o0 += xk * sW[k * D_OUT + l];
        o1 += xk * sW[k * D_OUT + 16 + l];
        if (has3) o2 += xk * sW[k * D_OUT + 32 + l];
    }
    float v0 = o0 + __ldg(&b2[l]);
    float v1 = o1 + __ldg(&b2[16 + l]);
    float v2 = has3 ? (o2 + __ldg(&b2[32 + l])) : -INFINITY;

    float mx = fmaxf(fmaxf(v0, v1), v2);
#pragma unroll
    for (int st = 8; st > 0; st >>= 1)
        mx = fmaxf(mx, __shfl_xor_sync(0xFFFFFFFFu, mx, st));
    float s = __expf(v0 - mx) + __expf(v1 - mx) + (has3 ? __expf(v2 - mx) : 0.f);
#pragma unroll
    for (int st = 8; st > 0; st >>= 1)
        s += __shfl_xor_sync(0xFFFFFFFFu, s, st);
    float lse = mx + __logf(s);

    float* r = out + (size_t)v * D_OUT;
    r[l] = v0 - lse;
    r[16 + l] = v1 - lse;
    if (has3) r[32 + l] = v2 - lse;
}

// ---------------- launch (PDL chain) ----------------
static inline void launch_pdl(void* fn, dim3 grid, dim3 block, void** args, bool pdl) {
    cudaLaunchConfig_t cfg = {};
    cfg.gridDim = grid;
    cfg.blockDim = block;
    cudaLaunchAttribute attr[1];
    if (pdl) {
        attr[0].id = cudaLaunchAttributeProgrammaticStreamSerialization;
        attr[0].val.programmaticStreamSerializationAllowed = 1;
        cfg.attrs = attr;
        cfg.numAttrs = 1;
    }
    cudaLaunchKernelExC(&cfg, fn, args);
}

extern "C" void kernel_launch(void* const* d_in, const int* in_sizes, int n_in,
                              void* d_out, int out_size) {
    const float* H   = (const float*)d_in[0];
    const float* w   = (const float*)d_in[1];
    const int*   ni  = (const int*)  d_in[2];
    const int*   ei  = (const int*)  d_in[3];
    const float* W1  = (const float*)d_in[4];
    const float* b1  = (const float*)d_in[5];
    const float* W2  = (const float*)d_in[6];
    const float* b2  = (const float*)d_in[7];
    float*       out = (float*)d_out;

    const int T = 256;
    auto blocks = [](long n, int t) { return (int)((n + t - 1) / t); };

    {
        void* args[] = {(void*)&H, (void*)&W1, (void*)&ni, (void*)&ei, (void*)&w};
        launch_pdl((void*)gemm1_fill_kernel, dim3(GEMM1_BLOCKS + FILL_BLOCKS), dim3(T), args, false);
    }
    {
        void* args[] = {};
        launch_pdl((void*)edge_gather1_kernel, dim3(N_EDGES / 4), dim3(T), args, true);
    }
    {
        void* args[] = {(void*)&b1};
        launch_pdl((void*)node_gather1_kernel, dim3(blocks((long)N_NODES * 16, T)), dim3(T), args, true);
    }
    {
        void* args[] = {};
        launch_pdl((void*)edge_gather2_kernel, dim3(N_EDGES / 4), dim3(T), args, true);
    }
    {
        void* args[] = {(void*)&out, (void*)&W2, (void*)&b2};
        launch_pdl((void*)node_gather2_fin_kernel, dim3(blocks((long)N_NODES * 16, T)), dim3(T), args, true);
    }
}

// round 17
// speedup vs baseline: 1.2665x; 1.2665x over previous
#include <cuda_runtime.h>
#include <cuda_bf16.h>
#include <cuda_fp16.h>
#include <math.h>

#define N_NODES 100000
#define N_EDGES 20000
#define N_INC   800000
#define D_IN    256
#define D_HID   16
#define D_OUT   40
#define PAD_E   128
#define PAD_V   64

// ---------------- scratch (device globals) ----------------
__device__ __half2 g_XW1h[(size_t)N_NODES * (D_HID / 2)]; // H@W1, fp16, 32B rows
__device__ __half2 g_e1h [(size_t)N_EDGES * (D_HID / 2)]; // e_feat1, fp16, 32B rows
__device__ __half2 g_X2h [(size_t)N_NODES * (D_HID / 2)]; // x=relu(...), fp16, 32B rows
__device__ __half2 g_e2h [(size_t)N_EDGES * (D_HID / 2)]; // e_feat2, fp16, 32B rows
__device__ int     g_cnt_e[N_EDGES];   // zero-init; re-zeroed by ng2 each call
__device__ int     g_cnt_v[N_NODES];   // zero-init; re-zeroed by ng2 each call
__device__ int2    g_buf_e[(size_t)N_EDGES * PAD_E];      // {node idx, w bits}
__device__ int     g_buf_v[(size_t)N_NODES * PAD_V];      // edge idx

__device__ __forceinline__ unsigned h2u(__half2 h) {
    return *reinterpret_cast<unsigned*>(&h);
}

// ---------------- GEMM1 (tensor core) + bucket fill (merged) -----------------
// GEMM: block = 256 thr = 8 warps; warp computes 16 rows x 16 cols over K=256
#define ROWS_PER_BLOCK 128
#define GEMM1_BLOCKS ((N_NODES + ROWS_PER_BLOCK - 1) / ROWS_PER_BLOCK)   // 782
#define FILL_BLOCKS  ((N_INC + 255) / 256)
__global__ void gemm1_fill_kernel(const float* __restrict__ H, const float* __restrict__ W1,
                                  const int* __restrict__ ni, const int* __restrict__ ei,
                                  const float* __restrict__ w) {
    if (blockIdx.x >= GEMM1_BLOCKS) {
        // ---- fill branch (unchanged) ----
        int i = (blockIdx.x - GEMM1_BLOCKS) * blockDim.x + threadIdx.x;
        if (i >= N_INC) return;
        int v = __ldg(&ni[i]);
        int e = __ldg(&ei[i]);
        float wv = __ldg(&w[v]);
        int se = atomicAdd(&g_cnt_e[e], 1);
        if (se < PAD_E) g_buf_e[(size_t)e * PAD_E + se] = make_int2(v, __float_as_int(wv));
        int sv = atomicAdd(&g_cnt_v[v], 1);
        if (sv < PAD_V) g_buf_v[(size_t)v * PAD_V + sv] = e;
        return;
    }
    // ---- tensor-core GEMM branch ----
    __shared__ __half wT[D_HID * D_IN];   // W1 transposed: wT[n*256 + k], 8KB
    for (int i = threadIdx.x; i < D_IN * D_HID; i += blockDim.x) {
        int k = i / D_HID, n = i - k * D_HID;
        wT[n * D_IN + k] = __float2half(W1[i]);
    }
    __syncthreads();

    int wib  = threadIdx.x >> 5;
    int lane = threadIdx.x & 31;
    int gID  = lane >> 2;         // 0..7
    int tig  = lane & 3;          // 0..3
    int rb   = (blockIdx.x * 8 + wib) * 16;

    int r0 = min(rb + gID,     N_NODES - 1);   // clamp OOB loads (stores guarded)
    int r1 = min(rb + gID + 8, N_NODES - 1);
    const float* h0 = H + (size_t)r0 * D_IN;
    const float* h1 = H + (size_t)r1 * D_IN;

    float c0[4] = {0.f, 0.f, 0.f, 0.f};   // n-cols 0..7
    float c1[4] = {0.f, 0.f, 0.f, 0.f};   // n-cols 8..15

    const __half* wt0 = wT + gID * D_IN;           // n = gID
    const __half* wt1 = wT + (gID + 8) * D_IN;     // n = gID+8

#pragma unroll
    for (int ks = 0; ks < D_IN / 16; ks++) {
        int k0 = ks * 16 + 2 * tig;
        // A fragments (fp32 -> fp16 inline)
        float2 p0 = __ldcs(reinterpret_cast<const float2*>(h0 + k0));
        float2 p1 = __ldcs(reinterpret_cast<const float2*>(h1 + k0));
        float2 p2 = __ldcs(reinterpret_cast<const float2*>(h0 + k0 + 8));
        float2 p3 = __ldcs(reinterpret_cast<const float2*>(h1 + k0 + 8));
        unsigned a0 = h2u(__floats2half2_rn(p0.x, p0.y));
        unsigned a1 = h2u(__floats2half2_rn(p1.x, p1.y));
        unsigned a2 = h2u(__floats2half2_rn(p2.x, p2.y));
        unsigned a3 = h2u(__floats2half2_rn(p3.x, p3.y));
        // B fragments from transposed smem (contiguous half pairs)
        unsigned b00 = *reinterpret_cast<const unsigned*>(wt0 + k0);
        unsigned b01 = *reinterpret_cast<const unsigned*>(wt0 + k0 + 8);
        unsigned b10 = *reinterpret_cast<const unsigned*>(wt1 + k0);
        unsigned b11 = *reinterpret_cast<const unsigned*>(wt1 + k0 + 8);

        asm volatile("mma.sync.aligned.m16n8k16.row.col.f32.f16.f16.f32 "
                     "{%0,%1,%2,%3}, {%4,%5,%6,%7}, {%8,%9}, {%0,%1,%2,%3};"
                     : "+f"(c0[0]), "+f"(c0[1]), "+f"(c0[2]), "+f"(c0[3])
                     : "r"(a0), "r"(a1), "r"(a2), "r"(a3), "r"(b00), "r"(b01));
        asm volatile("mma.sync.aligned.m16n8k16.row.col.f32.f16.f16.f32 "
                     "{%0,%1,%2,%3}, {%4,%5,%6,%7}, {%8,%9}, {%0,%1,%2,%3};"
                     : "+f"(c1[0]), "+f"(c1[1]), "+f"(c1[2]), "+f"(c1[3])
                     : "r"(a0), "r"(a1), "r"(a2), "r"(a3), "r"(b10), "r"(b11));
    }

    // store: row rb+gID gets {c0[0],c0[1]} at cols 2tig,2tig+1 and {c1[0],c1[1]} at 8+2tig
    //        row rb+gID+8 gets {c0[2],c0[3]} and {c1[2],c1[3]}
    unsigned* xw = reinterpret_cast<unsigned*>(g_XW1h);
    int rowA = rb + gID, rowB = rb + gID + 8;
    if (rowA < N_NODES) {
        xw[(size_t)rowA * 8 + tig]     = h2u(__floats2half2_rn(c0[0], c0[1]));
        xw[(size_t)rowA * 8 + 4 + tig] = h2u(__floats2half2_rn(c1[0], c1[1]));
    }
    if (rowB < N_NODES) {
        xw[(size_t)rowB * 8 + tig]     = h2u(__floats2half2_rn(c0[2], c0[3]));
        xw[(size_t)rowB * 8 + 4 + tig] = h2u(__floats2half2_rn(c1[2], c1[3]));
    }
}

// ---------------- edge gather 1: warp/edge, 8 groups x 4-lane uint2 ----------
__global__ void edge_gather1_kernel() {
    int warp = (blockIdx.x * blockDim.x + threadIdx.x) >> 5;
    int lane = threadIdx.x & 31;
    int g = lane >> 2, c = lane & 3;
    bool active = warp < N_EDGES;
    int e = active ? warp : 0;

    cudaGridDependencySynchronize();   // wait for gemm1_fill results
    if (!active) return;

    int cnt = min(__ldg(&g_cnt_e[e]), PAD_E);
    const int2* buf = g_buf_e + (size_t)e * PAD_E;
    const uint2* xr = reinterpret_cast<const uint2*>(g_XW1h);
    float4 acc = make_float4(0.f, 0.f, 0.f, 0.f);
    float wsum = 0.f;
    int mb = 0;
    for (; mb + 8 <= cnt; mb += 8) {
        int2 p = __ldg(&buf[mb + g]);
        float wv = __int_as_float(p.y);
        uint2 r = __ldg(&xr[(size_t)p.x * 4 + c]);
        float2 f0 = __half22float2(*reinterpret_cast<__half2*>(&r.x));
        float2 f1 = __half22float2(*reinterpret_cast<__half2*>(&r.y));
        acc.x += wv * f0.x; acc.y += wv * f0.y; acc.z += wv * f1.x; acc.w += wv * f1.y;
        wsum += wv;
    }
    if (mb + g < cnt) {
        int2 p = __ldg(&buf[mb + g]);
        float wv = __int_as_float(p.y);
        uint2 r = __ldg(&xr[(size_t)p.x * 4 + c]);
        float2 f0 = __half22float2(*reinterpret_cast<__half2*>(&r.x));
        float2 f1 = __half22float2(*reinterpret_cast<__half2*>(&r.y));
        acc.x += wv * f0.x; acc.y += wv * f0.y; acc.z += wv * f1.x; acc.w += wv * f1.y;
        wsum += wv;
    }
#pragma unroll
    for (int st = 4; st < 32; st <<= 1) {
        acc.x += __shfl_xor_sync(0xFFFFFFFFu, acc.x, st);
        acc.y += __shfl_xor_sync(0xFFFFFFFFu, acc.y, st);
        acc.z += __shfl_xor_sync(0xFFFFFFFFu, acc.z, st);
        acc.w += __shfl_xor_sync(0xFFFFFFFFu, acc.w, st);
        wsum  += __shfl_xor_sync(0xFFFFFFFFu, wsum,  st);
    }
    if (g == 0) {
        float inv = __frcp_rn(fmaxf(wsum, 1e-6f));
        uint2 r;
        *reinterpret_cast<__half2*>(&r.x) = __floats2half2_rn(acc.x * inv, acc.y * inv);
        *reinterpret_cast<__half2*>(&r.y) = __floats2half2_rn(acc.z * inv, acc.w * inv);
        reinterpret_cast<uint2*>(g_e1h)[(size_t)e * 4 + c] = r;
    }
}

// ---------------- node gather 1: TWO nodes/warp; x=relu(mean+b1) -> fp16 -----
__global__ void node_gather1_kernel(const float* __restrict__ b1) {
    int warp = (blockIdx.x * blockDim.x + threadIdx.x) >> 5;
    int lane = threadIdx.x & 31;
    int half = lane >> 4, l = lane & 15;
    int v = warp * 2 + half;
    int g = l >> 2, c = l & 3;
    float bias = __ldg(&b1[l]);     // harness input: safe pre-sync

    cudaGridDependencySynchronize();
    if (v >= N_NODES) return;

    int cnt = min(__ldg(&g_cnt_v[v]), PAD_V);
    const int* buf = g_buf_v + (size_t)v * PAD_V;
    const uint2* er = reinterpret_cast<const uint2*>(g_e1h);
    float4 acc = make_float4(0.f, 0.f, 0.f, 0.f);
    int mb = 0;
    for (; mb + 4 <= cnt; mb += 4) {
        int e0 = __ldg(&buf[mb + g]);
        uint2 r = __ldg(&er[(size_t)e0 * 4 + c]);
        float2 f0 = __half22float2(*reinterpret_cast<__half2*>(&r.x));
        float2 f1 = __half22float2(*reinterpret_cast<__half2*>(&r.y));
        acc.x += f0.x; acc.y += f0.y; acc.z += f1.x; acc.w += f1.y;
    }
    if (mb + g < cnt) {
        int e0 = __ldg(&buf[mb + g]);
        uint2 r = __ldg(&er[(size_t)e0 * 4 + c]);
        float2 f0 = __half22float2(*reinterpret_cast<__half2*>(&r.x));
        float2 f1 = __half22float2(*reinterpret_cast<__half2*>(&r.y));
        acc.x += f0.x; acc.y += f0.y; acc.z += f1.x; acc.w += f1.y;
    }
#pragma unroll
    for (int st = 4; st < 16; st <<= 1) {
        acc.x += __shfl_xor_sync(0xFFFFFFFFu, acc.x, st);
        acc.y += __shfl_xor_sync(0xFFFFFFFFu, acc.y, st);
        acc.z += __shfl_xor_sync(0xFFFFFFFFu, acc.z, st);
        acc.w += __shfl_xor_sync(0xFFFFFFFFu, acc.w, st);
    }
    if (g == 0) {
        float b0  = __shfl_sync(0xFFFFFFFFu, bias, (half << 4) + c * 4 + 0);
        float bb1 = __shfl_sync(0xFFFFFFFFu, bias, (half << 4) + c * 4 + 1);
        float b2v = __shfl_sync(0xFFFFFFFFu, bias, (half << 4) + c * 4 + 2);
        float b3  = __shfl_sync(0xFFFFFFFFu, bias, (half << 4) + c * 4 + 3);
        float invd = __frcp_rn(fmaxf((float)cnt, 1.f));
        float x0 = fmaxf(acc.x * invd + b0, 0.f);
        float x1 = fmaxf(acc.y * invd + bb1, 0.f);
        float x2 = fmaxf(acc.z * invd + b2v, 0.f);
        float x3 = fmaxf(acc.w * invd + b3, 0.f);
        uint2 r;
        *reinterpret_cast<__half2*>(&r.x) = __floats2half2_rn(x0, x1);
        *reinterpret_cast<__half2*>(&r.y) = __floats2half2_rn(x2, x3);
        reinterpret_cast<uint2*>(g_X2h)[(size_t)v * 4 + c] = r;
    }
}

// ---------------- edge gather 2: identical structure on X2 -------------------
__global__ void edge_gather2_kernel() {
    int warp = (blockIdx.x * blockDim.x + threadIdx.x) >> 5;
    int lane = threadIdx.x & 31;
    int g = lane >> 2, c = lane & 3;
    bool active = warp < N_EDGES;
    int e = active ? warp : 0;

    cudaGridDependencySynchronize();
    if (!active) return;

    int cnt = min(__ldg(&g_cnt_e[e]), PAD_E);
    const int2* buf = g_buf_e + (size_t)e * PAD_E;
    const uint2* xr = reinterpret_cast<const uint2*>(g_X2h);
    float4 acc = make_float4(0.f, 0.f, 0.f, 0.f);
    float wsum = 0.f;
    int mb = 0;
    for (; mb + 8 <= cnt; mb += 8) {
        int2 p = __ldg(&buf[mb + g]);
        float wv = __int_as_float(p.y);
        uint2 r = __ldg(&xr[(size_t)p.x * 4 + c]);
        float2 f0 = __half22float2(*reinterpret_cast<__half2*>(&r.x));
        float2 f1 = __half22float2(*reinterpret_cast<__half2*>(&r.y));
        acc.x += wv * f0.x; acc.y += wv * f0.y; acc.z += wv * f1.x; acc.w += wv * f1.y;
        wsum += wv;
    }
    if (mb + g < cnt) {
        int2 p = __ldg(&buf[mb + g]);
        float wv = __int_as_float(p.y);
        uint2 r = __ldg(&xr[(size_t)p.x * 4 + c]);
        float2 f0 = __half22float2(*reinterpret_cast<__half2*>(&r.x));
        float2 f1 = __half22float2(*reinterpret_cast<__half2*>(&r.y));
        acc.x += wv * f0.x; acc.y += wv * f0.y; acc.z += wv * f1.x; acc.w += wv * f1.y;
        wsum += wv;
    }
#pragma unroll
    for (int st = 4; st < 32; st <<= 1) {
        acc.x += __shfl_xor_sync(0xFFFFFFFFu, acc.x, st);
        acc.y += __shfl_xor_sync(0xFFFFFFFFu, acc.y, st);
        acc.z += __shfl_xor_sync(0xFFFFFFFFu, acc.z, st);
        acc.w += __shfl_xor_sync(0xFFFFFFFFu, acc.w, st);
        wsum  += __shfl_xor_sync(0xFFFFFFFFu, wsum,  st);
    }
    if (g == 0) {
        float inv = __frcp_rn(fmaxf(wsum, 1e-6f));
        uint2 r;
        *reinterpret_cast<__half2*>(&r.x) = __floats2half2_rn(acc.x * inv, acc.y * inv);
        *reinterpret_cast<__half2*>(&r.y) = __floats2half2_rn(acc.z * inv, acc.w * inv);
        reinterpret_cast<uint2*>(g_e2h)[(size_t)e * 4 + c] = r;
    }
}

// ---------------- node gather 2: TWO nodes/warp + W2 + b2 + log_softmax ------
__global__ void node_gather2_fin_kernel(float* __restrict__ out,
                                        const float* __restrict__ W2,
                                        const float* __restrict__ b2) {
    __shared__ float sW[D_HID * D_OUT];
    for (int i = threadIdx.x; i < D_HID * D_OUT; i += blockDim.x) sW[i] = W2[i];
    __syncthreads();

    cudaGridDependencySynchronize();

    int warp = (blockIdx.x * blockDim.x + threadIdx.x) >> 5;
    int lane = threadIdx.x & 31;
    int half = lane >> 4, l = lane & 15;
    int v = warp * 2 + half;
    if (v >= N_NODES) return;
    int cnt = min(__ldg(&g_cnt_v[v]), PAD_V);
    if (l == 0) g_cnt_v[v] = 0;
    if (l == 1 && v < N_EDGES) g_cnt_e[v] = 0;
    int g = l >> 2, c = l & 3;

    const int* buf = g_buf_v + (size_t)v * PAD_V;
    const uint2* er = reinterpret_cast<const uint2*>(g_e2h);
    float4 acc = make_float4(0.f, 0.f, 0.f, 0.f);
    int mb = 0;
    for (; mb + 4 <= cnt; mb += 4) {
        int e0 = __ldg(&buf[mb + g]);
        uint2 r = __ldg(&er[(size_t)e0 * 4 + c]);
        float2 f0 = __half22float2(*reinterpret_cast<__half2*>(&r.x));
        float2 f1 = __half22float2(*reinterpret_cast<__half2*>(&r.y));
        acc.x += f0.x; acc.y += f0.y; acc.z += f1.x; acc.w += f1.y;
    }
    if (mb + g < cnt) {
        int e0 = __ldg(&buf[mb + g]);
        uint2 r = __ldg(&er[(size_t)e0 * 4 + c]);
        float2 f0 = __half22float2(*reinterpret_cast<__half2*>(&r.x));
        float2 f1 = __half22float2(*reinterpret_cast<__half2*>(&r.y));
        acc.x += f0.x; acc.y += f0.y; acc.z += f1.x; acc.w += f1.y;
    }
#pragma unroll
    for (int st = 4; st < 16; st <<= 1) {
        acc.x += __shfl_xor_sync(0xFFFFFFFFu, acc.x, st);
        acc.y += __shfl_xor_sync(0xFFFFFFFFu, acc.y, st);
        acc.z += __shfl_xor_sync(0xFFFFFFFFu, acc.z, st);
        acc.w += __shfl_xor_sync(0xFFFFFFFFu, acc.w, st);
    }
    float invd = __frcp_rn(fmaxf((float)cnt, 1.f));
    float4 vf;
    vf.x = acc.x * invd; vf.y = acc.y * invd; vf.z = acc.z * invd; vf.w = acc.w * invd;

    bool has3 = l < (D_OUT - 32);
    float o0 = 0.f, o1 = 0.f, o2 = 0.f;
#pragma unroll
    for (int k = 0; k < D_HID; k++) {
        int src = (half << 4) + (k >> 2);
        float comp = (k & 3) == 0 ? vf.x : (k & 3) == 1 ? vf.y : (k & 3) == 2 ? vf.z : vf.w;
        float xk = __shfl_sync(0xFFFFFFFFu, comp, src);
        o0 += xk * sW[k * D_OUT + l];
        o1 += xk * sW[k * D_OUT + 16 + l];
        if (has3) o2 += xk * sW[k * D_OUT + 32 + l];
    }
    float v0 = o0 + __ldg(&b2[l]);
    float v1 = o1 + __ldg(&b2[16 + l]);
    float v2 = has3 ? (o2 + __ldg(&b2[32 + l])) : -INFINITY;

    float mx = fmaxf(fmaxf(v0, v1), v2);
#pragma unroll
    for (int st = 8; st > 0; st >>= 1)
        mx = fmaxf(mx, __shfl_xor_sync(0xFFFFFFFFu, mx, st));
    float s = __expf(v0 - mx) + __expf(v1 - mx) + (has3 ? __expf(v2 - mx) : 0.f);
#pragma unroll
    for (int st = 8; st > 0; st >>= 1)
        s += __shfl_xor_sync(0xFFFFFFFFu, s, st);
    float lse = mx + __logf(s);

    float* r = out + (size_t)v * D_OUT;
    r[l] = v0 - lse;
    r[16 + l] = v1 - lse;
    if (has3) r[32 + l] = v2 - lse;
}

// ---------------- launch (PDL chain) ----------------
static inline void launch_pdl(void* fn, dim3 grid, dim3 block, void** args, bool pdl) {
    cudaLaunchConfig_t cfg = {};
    cfg.gridDim = grid;
    cfg.blockDim = block;
    cudaLaunchAttribute attr[1];
    if (pdl) {
        attr[0].id = cudaLaunchAttributeProgrammaticStreamSerialization;
        attr[0].val.programmaticStreamSerializationAllowed = 1;
        cfg.attrs = attr;
        cfg.numAttrs = 1;
    }
    cudaLaunchKernelExC(&cfg, fn, args);
}

extern "C" void kernel_launch(void* const* d_in, const int* in_sizes, int n_in,
                              void* d_out, int out_size) {
    const float* H   = (const float*)d_in[0];
    const float* w   = (const float*)d_in[1];
    const int*   ni  = (const int*)  d_in[2];
    const int*   ei  = (const int*)  d_in[3];
    const float* W1  = (const float*)d_in[4];
    const float* b1  = (const float*)d_in[5];
    const float* W2  = (const float*)d_in[6];
    const float* b2  = (const float*)d_in[7];
    float*       out = (float*)d_out;

    const int T = 256;
    auto blocks = [](long n, int t) { return (int)((n + t - 1) / t); };

    {
        void* args[] = {(void*)&H, (void*)&W1, (void*)&ni, (void*)&ei, (void*)&w};
        launch_pdl((void*)gemm1_fill_kernel, dim3(GEMM1_BLOCKS + FILL_BLOCKS), dim3(T), args, false);
    }
    {
        void* args[] = {};
        launch_pdl((void*)edge_gather1_kernel, dim3(blocks((long)N_EDGES * 32, T)), dim3(T), args, true);
    }
    {
        void* args[] = {(void*)&b1};
        launch_pdl((void*)node_gather1_kernel, dim3(blocks((long)N_NODES * 16, T)), dim3(T), args, true);
    }
    {
        void* args[] = {};
        launch_pdl((void*)edge_gather2_kernel, dim3(blocks((long)N_EDGES * 32, T)), dim3(T), args, true);
    }
    {
        void* args[] = {(void*)&out, (void*)&W2, (void*)&b2};
        launch_pdl((void*)node_gather2_fin_kernel, dim3(blocks((long)N_NODES * 16, T)), dim3(T), args, true);
    }
}